// round 6
// baseline (speedup 1.0000x reference)
#include <cuda_runtime.h>
#include <cuda.h>
#include <cstdint>

// ---------------------------------------------------------------------------
// Problem constants
// ---------------------------------------------------------------------------
#define BB   16
#define CI   256
#define CO   256
#define NTAP 9
#define KTOT 2304          // 9*256
#define NPOS 65536         // B*H*W

// Scratch (device globals: allocation-free per harness rules)
__device__ unsigned g_xa[(size_t)NPOS * CI];   // tf32( x * (style+1) ), [b,h,w,ci]
__device__ unsigned g_Wt[(size_t)CO * KTOT];   // tf32( kernel ) transposed: [co][k]
__device__ float    g_K2[CI * CO];
__device__ float    g_dmod[BB * CO];

__device__ __forceinline__ unsigned f2tf(float f) {
    unsigned u; asm("cvt.rna.tf32.f32 %0, %1;" : "=r"(u) : "f"(f)); return u;
}

// ---------------------------------------------------------------------------
// Prep kernels
// ---------------------------------------------------------------------------
__global__ void k2_kernel(const float* __restrict__ kern) {
    int ci = blockIdx.x, co = threadIdx.x;
    float s = 0.f;
#pragma unroll
    for (int t = 0; t < NTAP; ++t) {
        float v = kern[(t * CI + ci) * CO + co];
        s += v * v;
    }
    g_K2[ci * CO + co] = s;
}

__global__ void dmod_kernel(const float* __restrict__ style) {
    __shared__ float sm2[CI];
    int b = blockIdx.x, co = threadIdx.x;
    float st = style[b * CI + co] + 1.f;
    sm2[co] = st * st;
    __syncthreads();
    float acc = 1e-8f;
#pragma unroll 8
    for (int ci = 0; ci < CI; ++ci) acc += sm2[ci] * g_K2[ci * CO + co];
    g_dmod[b * CO + co] = rsqrtf(acc);
}

// g_Wt[co][k] = tf32(kern[k][co])
__global__ void wt_kernel(const float* __restrict__ kern) {
    __shared__ float t[32][33];
    int kk0 = blockIdx.x * 32, co0 = blockIdx.y * 32;
    int tx = threadIdx.x, ty = threadIdx.y;   // 32 x 8
#pragma unroll
    for (int j = 0; j < 4; ++j)
        t[ty + 8 * j][tx] = kern[(size_t)(kk0 + ty + 8 * j) * CO + co0 + tx];
    __syncthreads();
#pragma unroll
    for (int j = 0; j < 4; ++j)
        g_Wt[(size_t)(co0 + ty + 8 * j) * KTOT + kk0 + tx] = f2tf(t[tx][ty + 8 * j]);
}

__global__ void xa_kernel(const float* __restrict__ x, const float* __restrict__ style) {
    unsigned i = blockIdx.x * 256 + threadIdx.x;   // float4 units
    const float4 v = ((const float4*)x)[i];
    unsigned idx = i * 4;
    unsigned ci = idx & 255u, b = idx >> 20;
    const float4 s = *(const float4*)&style[b * CI + ci];
    uint4 o;
    o.x = f2tf(v.x * (s.x + 1.f));
    o.y = f2tf(v.y * (s.y + 1.f));
    o.z = f2tf(v.z * (s.z + 1.f));
    o.w = f2tf(v.w * (s.w + 1.f));
    ((uint4*)g_xa)[i] = o;
}

// ---------------------------------------------------------------------------
// Main GEMM: M=65536, N=256, K=2304. CTA 256x128, warp 64x64, Ktile=32,
// 4-stage TMA + mbarrier pipeline, double-buffered ldmatrix frags, mma tf32.
// ---------------------------------------------------------------------------
static __device__ __forceinline__ uint32_t smem_u32(const void* p) {
    uint32_t a;
    asm("{ .reg .u64 t; cvta.to.shared.u64 t, %1; cvt.u32.u64 %0, t; }" : "=r"(a) : "l"(p));
    return a;
}
__device__ __forceinline__ void mbar_init(uint32_t a, uint32_t cnt) {
    asm volatile("mbarrier.init.shared.b64 [%0], %1;" :: "r"(a), "r"(cnt) : "memory");
}
__device__ __forceinline__ void mbar_wait(uint32_t a, int parity) {
    asm volatile(
        "{\n\t.reg .pred P;\n\t"
        "WL_%=:\n\t"
        "mbarrier.try_wait.parity.acquire.cta.shared::cta.b64 P, [%0], %1, 0x989680;\n\t"
        "@P bra.uni WD_%=;\n\t"
        "bra.uni WL_%=;\n\t"
        "WD_%=:\n\t}"
        :: "r"(a), "r"(parity) : "memory");
}
__device__ __forceinline__ void mbar_wait_relaxed(uint32_t a, int parity) {
    asm volatile(
        "{\n\t.reg .pred P;\n\t"
        "WL_%=:\n\t"
        "mbarrier.try_wait.parity.relaxed.cta.shared::cta.b64 P, [%0], %1, 0x989680;\n\t"
        "@P bra.uni WD_%=;\n\t"
        "bra.uni WL_%=;\n\t"
        "WD_%=:\n\t}"
        :: "r"(a), "r"(parity) : "memory");
}
__device__ __forceinline__ void mbar_arrive(uint32_t a) {
    asm volatile("mbarrier.arrive.shared.b64 _, [%0];" :: "r"(a) : "memory");
}
__device__ __forceinline__ void mbar_expect_tx(uint32_t a, uint32_t tx) {
    asm volatile("mbarrier.arrive.expect_tx.shared.b64 _, [%0], %1;" :: "r"(a), "r"(tx) : "memory");
}
__device__ __forceinline__ void tma4d(uint32_t dst, const CUtensorMap* m,
                                      int c0, int c1, int c2, int c3, uint32_t bar) {
    asm volatile(
        "cp.async.bulk.tensor.4d.shared::cta.global.tile.mbarrier::complete_tx::bytes "
        "[%0], [%1, {%2,%3,%4,%5}], [%6];"
        :: "r"(dst), "l"(m), "r"(c0), "r"(c1), "r"(c2), "r"(c3), "r"(bar) : "memory");
}
__device__ __forceinline__ void tma2d(uint32_t dst, const CUtensorMap* m,
                                      int c0, int c1, uint32_t bar) {
    asm volatile(
        "cp.async.bulk.tensor.2d.shared::cta.global.tile.mbarrier::complete_tx::bytes "
        "[%0], [%1, {%2,%3}], [%4];"
        :: "r"(dst), "l"(m), "r"(c0), "r"(c1), "r"(bar) : "memory");
}
__device__ __forceinline__ void ldsm4(unsigned& r0, unsigned& r1, unsigned& r2, unsigned& r3,
                                      uint32_t a) {
    asm volatile("ldmatrix.sync.aligned.m8n8.x4.shared.b16 {%0,%1,%2,%3}, [%4];"
                 : "=r"(r0), "=r"(r1), "=r"(r2), "=r"(r3) : "r"(a));
}
__device__ __forceinline__ void mma_tf32(float& d0, float& d1, float& d2, float& d3,
                                         unsigned a0, unsigned a1, unsigned a2, unsigned a3,
                                         unsigned b0, unsigned b1) {
    asm volatile(
        "mma.sync.aligned.m16n8k8.row.col.f32.tf32.tf32.f32 "
        "{%0,%1,%2,%3}, {%4,%5,%6,%7}, {%8,%9}, {%0,%1,%2,%3};\n"
        : "+f"(d0), "+f"(d1), "+f"(d2), "+f"(d3)
        : "r"(a0), "r"(a1), "r"(a2), "r"(a3), "r"(b0), "r"(b1));
}

#define A_BYTES 32768       // 256 rows * 128B
#define B_BYTES 16384       // 128 rows * 128B
#define STAGE_BYTES (A_BYTES + B_BYTES)
#define NSTAGE 4
#define SMEM_DYN (NSTAGE * STAGE_BYTES + 1024)
#define KITERS 72

__global__ __launch_bounds__(256, 1)
void modconv_main(const __grid_constant__ CUtensorMap amap,
                  const __grid_constant__ CUtensorMap bmap,
                  float* __restrict__ out) {
    extern __shared__ char smem[];
    __shared__ __align__(8) unsigned long long bar_store[2 * NSTAGE];
    __shared__ float s_dmod[128];

    const uint32_t S = (smem_u32(smem) + 1023u) & ~1023u;
    const uint32_t barb = smem_u32(bar_store);

    const int tid  = threadIdx.x;
    const int wid  = tid >> 5;
    const int lane = tid & 31;

    const int n0   = blockIdx.x << 7;
    const int pos0 = blockIdx.y << 8;       // 256 rows = 4 image rows of one image
    const int b    = pos0 >> 12;
    const int h0   = (pos0 >> 6) & 63;

    if (tid == 0) {
#pragma unroll
        for (int s = 0; s < NSTAGE; ++s) {
            mbar_init(barb + 16 * s, 1);        // full[s]
            mbar_init(barb + 16 * s + 8, 8);    // empty[s]: one arrive per warp
        }
    }
    if (tid < 128) s_dmod[tid] = g_dmod[b * CO + n0 + tid];
    __syncthreads();

    auto issue = [&](int kt) {
        const int s = kt & 3;
        mbar_wait_relaxed(barb + 16 * s + 8, ((kt >> 2) & 1) ^ 1);   // empty[s]
        const uint32_t fb = barb + 16 * s;
        mbar_expect_tx(fb, STAGE_BYTES);
        const int tap = kt >> 3;
        const int ci0 = (kt & 7) * 32;
        const int dh  = tap / 3 - 1;
        const int dw  = tap - (tap / 3) * 3 - 1;
        tma4d(S + s * STAGE_BYTES, &amap, ci0, dw, h0 + dh, b, fb);
        tma2d(S + s * STAGE_BYTES + A_BYTES, &bmap, kt * 32, n0, fb);
    };

    // fragment geometry
    const int g  = lane >> 3;
    const int rr = lane & 7;
    const int warpM = (wid >> 1) << 6;      // 4 M-warps
    const int warpN = (wid & 1) << 6;       // 2 N-warps
    const uint32_t swx = (uint32_t)rr << 4;
    const uint32_t a_chi = (uint32_t)(g >> 1) << 4;
    const uint32_t b_chi = (uint32_t)(g & 1) << 4;
    const int a_rl = rr + ((g & 1) << 3);
    const int b_rl = rr + ((g >> 1) << 3);
    uint32_t a_row[4], b_row[4];
#pragma unroll
    for (int mt = 0; mt < 4; ++mt) a_row[mt] = (uint32_t)(warpM + mt * 16 + a_rl) << 7;
#pragma unroll
    for (int np = 0; np < 4; ++np) b_row[np] = (uint32_t)(warpN + np * 16 + b_rl) << 7;

    float acc[4][8][4];
#pragma unroll
    for (int mt = 0; mt < 4; ++mt)
#pragma unroll
        for (int nt = 0; nt < 8; ++nt)
#pragma unroll
            for (int i = 0; i < 4; ++i) acc[mt][nt][i] = 0.f;

    // double-buffered fragments
    unsigned af[2][4][4], bf[2][4][4];

    auto ldfrag = [&](uint32_t As, uint32_t Bs, int ks, int pb) {
        const uint32_t ca = ((uint32_t)(ks * 32) + a_chi) ^ swx;
        const uint32_t cb = ((uint32_t)(ks * 32) + b_chi) ^ swx;
#pragma unroll
        for (int mt = 0; mt < 4; ++mt)
            ldsm4(af[pb][mt][0], af[pb][mt][1], af[pb][mt][2], af[pb][mt][3],
                  As + a_row[mt] + ca);
#pragma unroll
        for (int np = 0; np < 4; ++np)
            ldsm4(bf[pb][np][0], bf[pb][np][1], bf[pb][np][2], bf[pb][np][3],
                  Bs + b_row[np] + cb);
    };

    // prologue: warps 0..2 (lane 0) issue stages 0..2
    if (lane == 0 && wid < 3) issue(wid);

#pragma unroll 1
    for (int kt = 0; kt < KITERS; ++kt) {
        // rotating producer: warp (kt+3)&7 issues the stage 3 ahead
        if (kt + 3 < KITERS && lane == 0 && wid == ((kt + 3) & 7)) issue(kt + 3);

        const int s = kt & 3;
        mbar_wait(barb + 16 * s, (kt >> 2) & 1);   // full[s]

        const uint32_t As = S + s * STAGE_BYTES;
        const uint32_t Bs = As + A_BYTES;

        ldfrag(As, Bs, 0, 0);
#pragma unroll
        for (int ks = 0; ks < 4; ++ks) {
            const int cur = ks & 1;
            if (ks < 3) ldfrag(As, Bs, ks + 1, cur ^ 1);   // prefetch next k-step
#pragma unroll
            for (int mt = 0; mt < 4; ++mt)
#pragma unroll
                for (int nt = 0; nt < 8; ++nt) {
                    const unsigned bb0 = bf[cur][nt >> 1][(nt & 1) * 2];
                    const unsigned bb1 = bf[cur][nt >> 1][(nt & 1) * 2 + 1];
                    mma_tf32(acc[mt][nt][0], acc[mt][nt][1], acc[mt][nt][2], acc[mt][nt][3],
                             af[cur][mt][0], af[cur][mt][1], af[cur][mt][2], af[cur][mt][3],
                             bb0, bb1);
                }
        }
        if (lane == 0) mbar_arrive(barb + 16 * s + 8);   // empty[s]
    }

    // epilogue: demodulate + streaming store
    const int ar = lane >> 2, ac = lane & 3;
#pragma unroll
    for (int mt = 0; mt < 4; ++mt) {
#pragma unroll
        for (int nt = 0; nt < 8; ++nt) {
            const int r = warpM + mt * 16 + ar;
            const int c = warpN + nt * 8 + ac * 2;
            const float d0 = s_dmod[c], d1 = s_dmod[c + 1];
            const size_t base = (size_t)(pos0 + r) * CO + n0 + c;
            float2 o0 = { acc[mt][nt][0] * d0, acc[mt][nt][1] * d1 };
            __stcs((float2*)&out[base], o0);
            float2 o1 = { acc[mt][nt][2] * d0, acc[mt][nt][3] * d1 };
            __stcs((float2*)&out[base + (size_t)8 * CO], o1);
        }
    }
}

// ---------------------------------------------------------------------------
typedef CUresult (*EncodeFn)(CUtensorMap*, CUtensorMapDataType, cuuint32_t, void*,
                             const cuuint64_t*, const cuuint64_t*, const cuuint32_t*,
                             const cuuint32_t*, CUtensorMapInterleave, CUtensorMapSwizzle,
                             CUtensorMapL2promotion, CUtensorMapFloatOOBfill);

extern "C" void kernel_launch(void* const* d_in, const int* in_sizes, int n_in,
                              void* d_out, int out_size) {
    const float* x     = (const float*)d_in[0];
    const float* style = (const float*)d_in[1];
    const float* kern  = (const float*)d_in[2];
    float* out = (float*)d_out;

    cudaFuncSetAttribute(modconv_main, cudaFuncAttributeMaxDynamicSharedMemorySize, SMEM_DYN);

    void* xaptr = nullptr; cudaGetSymbolAddress(&xaptr, g_xa);
    void* wtptr = nullptr; cudaGetSymbolAddress(&wtptr, g_Wt);

    EncodeFn enc = nullptr;
    cudaDriverEntryPointQueryResult qst;
    cudaGetDriverEntryPointByVersion("cuTensorMapEncodeTiled", (void**)&enc, 12000,
                                     cudaEnableDefault, &qst);
    if (!enc) {
        cudaGetDriverEntryPoint("cuTensorMapEncodeTiled", (void**)&enc,
                                cudaEnableDefault, &qst);
    }

    CUtensorMap amap, bmap;
    {   // A: g_xa viewed as (ci=256, w=64, h=64, b=16), box (32, 64, 4, 1)
        cuuint64_t dims[4] = {256, 64, 64, 16};
        cuuint64_t strd[3] = {1024, 65536, 4194304};
        cuuint32_t box[4]  = {32, 64, 4, 1};
        cuuint32_t els[4]  = {1, 1, 1, 1};
        enc(&amap, CU_TENSOR_MAP_DATA_TYPE_FLOAT32, 4, xaptr, dims, strd, box, els,
            CU_TENSOR_MAP_INTERLEAVE_NONE, CU_TENSOR_MAP_SWIZZLE_128B,
            CU_TENSOR_MAP_L2_PROMOTION_L2_128B, CU_TENSOR_MAP_FLOAT_OOB_FILL_NONE);
    }
    {   // B: g_Wt viewed as (k=2304, co=256), box (32, 128)
        cuuint64_t dims[2] = {2304, 256};
        cuuint64_t strd[1] = {9216};
        cuuint32_t box[2]  = {32, 128};
        cuuint32_t els[2]  = {1, 1};
        enc(&bmap, CU_TENSOR_MAP_DATA_TYPE_FLOAT32, 2, wtptr, dims, strd, box, els,
            CU_TENSOR_MAP_INTERLEAVE_NONE, CU_TENSOR_MAP_SWIZZLE_128B,
            CU_TENSOR_MAP_L2_PROMOTION_L2_128B, CU_TENSOR_MAP_FLOAT_OOB_FILL_NONE);
    }

    k2_kernel<<<CI, CO>>>(kern);
    dmod_kernel<<<BB, CO>>>(style);
    wt_kernel<<<dim3(KTOT / 32, CO / 32), dim3(32, 8)>>>(kern);
    xa_kernel<<<(NPOS * CI) / 1024, 256>>>(x, style);

    modconv_main<<<dim3(2, NPOS / 256), 256, SMEM_DYN>>>(amap, bmap, out);
}

// round 9
// speedup vs baseline: 1.8087x; 1.8087x over previous
#include <cuda_runtime.h>
#include <cuda.h>
#include <cuda_fp16.h>
#include <cstdint>
#include <cstring>

// ---------------------------------------------------------------------------
// Problem constants
// ---------------------------------------------------------------------------
#define BB   16
#define CI   256
#define CO   256
#define NTAP 9
#define KTOT 2304          // 9*256
#define NPOS 65536         // B*H*W

// Scratch (device globals: allocation-free per harness rules)
__device__ unsigned short g_xa[(size_t)NPOS * CI];   // fp16( x * (style+1) ), [b,h,w,ci]
__device__ unsigned short g_Wt[(size_t)CO * KTOT];   // fp16( kernel ) transposed: [co][k]
__device__ float g_K2[CI * CO];
__device__ float g_dmod[BB * CO];

__device__ __forceinline__ unsigned h2u(__half2 h) {
    unsigned u;
    memcpy(&u, &h, 4);
    return u;
}

// ---------------------------------------------------------------------------
// Prep kernels
// ---------------------------------------------------------------------------
__global__ void k2_kernel(const float* __restrict__ kern) {
    int ci = blockIdx.x, co = threadIdx.x;
    float s = 0.f;
#pragma unroll
    for (int t = 0; t < NTAP; ++t) {
        float v = kern[(t * CI + ci) * CO + co];
        s += v * v;
    }
    g_K2[ci * CO + co] = s;
}

__global__ void dmod_kernel(const float* __restrict__ style) {
    __shared__ float sm2[CI];
    int b = blockIdx.x, co = threadIdx.x;
    float st = style[b * CI + co] + 1.f;
    sm2[co] = st * st;
    __syncthreads();
    float acc = 1e-8f;
#pragma unroll 8
    for (int ci = 0; ci < CI; ++ci) acc += sm2[ci] * g_K2[ci * CO + co];
    g_dmod[b * CO + co] = rsqrtf(acc);
}

// g_Wt[co][k] = fp16(kern[k][co])
__global__ void wt_kernel(const float* __restrict__ kern) {
    __shared__ float t[32][33];
    int kk0 = blockIdx.x * 32, co0 = blockIdx.y * 32;
    int tx = threadIdx.x, ty = threadIdx.y;   // 32 x 8
#pragma unroll
    for (int j = 0; j < 4; ++j)
        t[ty + 8 * j][tx] = kern[(size_t)(kk0 + ty + 8 * j) * CO + co0 + tx];
    __syncthreads();
#pragma unroll
    for (int j = 0; j < 4; ++j)
        g_Wt[(size_t)(co0 + ty + 8 * j) * KTOT + kk0 + tx] =
            __half_as_ushort(__float2half_rn(t[tx][ty + 8 * j]));
}

// g_xa = fp16( x * (style+1) ); 8 elements per thread
__global__ void xa_kernel(const float* __restrict__ x, const float* __restrict__ style) {
    unsigned i = blockIdx.x * 256 + threadIdx.x;     // 8-elem units
    const float4 v0 = ((const float4*)x)[2 * i];
    const float4 v1 = ((const float4*)x)[2 * i + 1];
    unsigned idx = i * 8;
    unsigned ci = idx & 255u, b = idx >> 20;
    const float4 s0 = *(const float4*)&style[b * CI + ci];
    const float4 s1 = *(const float4*)&style[b * CI + ci + 4];
    uint4 o;
    o.x = h2u(__floats2half2_rn(v0.x * (s0.x + 1.f), v0.y * (s0.y + 1.f)));
    o.y = h2u(__floats2half2_rn(v0.z * (s0.z + 1.f), v0.w * (s0.w + 1.f)));
    o.z = h2u(__floats2half2_rn(v1.x * (s1.x + 1.f), v1.y * (s1.y + 1.f)));
    o.w = h2u(__floats2half2_rn(v1.z * (s1.z + 1.f), v1.w * (s1.w + 1.f)));
    ((uint4*)g_xa)[i] = o;
}

// ---------------------------------------------------------------------------
// Main GEMM: M=65536, N=256, K=2304 (fp16). CTA 256x128, warp 64x64,
// Ktile=64 halves (128B rows), 4-stage TMA pipeline, ldmatrix + mma m16n8k16.
// ---------------------------------------------------------------------------
static __device__ __forceinline__ uint32_t smem_u32(const void* p) {
    uint32_t a;
    asm("{ .reg .u64 t; cvta.to.shared.u64 t, %1; cvt.u32.u64 %0, t; }" : "=r"(a) : "l"(p));
    return a;
}
__device__ __forceinline__ void mbar_init(uint32_t a, uint32_t cnt) {
    asm volatile("mbarrier.init.shared.b64 [%0], %1;" :: "r"(a), "r"(cnt) : "memory");
}
__device__ __forceinline__ void mbar_wait(uint32_t a, int parity) {
    asm volatile(
        "{\n\t.reg .pred P;\n\t"
        "WL_%=:\n\t"
        "mbarrier.try_wait.parity.acquire.cta.shared::cta.b64 P, [%0], %1, 0x989680;\n\t"
        "@P bra.uni WD_%=;\n\t"
        "bra.uni WL_%=;\n\t"
        "WD_%=:\n\t}"
        :: "r"(a), "r"(parity) : "memory");
}
__device__ __forceinline__ void mbar_wait_relaxed(uint32_t a, int parity) {
    asm volatile(
        "{\n\t.reg .pred P;\n\t"
        "WL_%=:\n\t"
        "mbarrier.try_wait.parity.relaxed.cta.shared::cta.b64 P, [%0], %1, 0x989680;\n\t"
        "@P bra.uni WD_%=;\n\t"
        "bra.uni WL_%=;\n\t"
        "WD_%=:\n\t}"
        :: "r"(a), "r"(parity) : "memory");
}
__device__ __forceinline__ void mbar_arrive(uint32_t a) {
    asm volatile("mbarrier.arrive.shared.b64 _, [%0];" :: "r"(a) : "memory");
}
__device__ __forceinline__ void mbar_expect_tx(uint32_t a, uint32_t tx) {
    asm volatile("mbarrier.arrive.expect_tx.shared.b64 _, [%0], %1;" :: "r"(a), "r"(tx) : "memory");
}
__device__ __forceinline__ void tma4d(uint32_t dst, const CUtensorMap* m,
                                      int c0, int c1, int c2, int c3, uint32_t bar) {
    asm volatile(
        "cp.async.bulk.tensor.4d.shared::cta.global.tile.mbarrier::complete_tx::bytes "
        "[%0], [%1, {%2,%3,%4,%5}], [%6];"
        :: "r"(dst), "l"(m), "r"(c0), "r"(c1), "r"(c2), "r"(c3), "r"(bar) : "memory");
}
__device__ __forceinline__ void tma2d(uint32_t dst, const CUtensorMap* m,
                                      int c0, int c1, uint32_t bar) {
    asm volatile(
        "cp.async.bulk.tensor.2d.shared::cta.global.tile.mbarrier::complete_tx::bytes "
        "[%0], [%1, {%2,%3}], [%4];"
        :: "r"(dst), "l"(m), "r"(c0), "r"(c1), "r"(bar) : "memory");
}
__device__ __forceinline__ void ldsm4(unsigned& r0, unsigned& r1, unsigned& r2, unsigned& r3,
                                      uint32_t a) {
    asm volatile("ldmatrix.sync.aligned.m8n8.x4.shared.b16 {%0,%1,%2,%3}, [%4];"
                 : "=r"(r0), "=r"(r1), "=r"(r2), "=r"(r3) : "r"(a));
}
__device__ __forceinline__ void mma_f16(float& d0, float& d1, float& d2, float& d3,
                                        unsigned a0, unsigned a1, unsigned a2, unsigned a3,
                                        unsigned b0, unsigned b1) {
    asm volatile(
        "mma.sync.aligned.m16n8k16.row.col.f32.f16.f16.f32 "
        "{%0,%1,%2,%3}, {%4,%5,%6,%7}, {%8,%9}, {%0,%1,%2,%3};\n"
        : "+f"(d0), "+f"(d1), "+f"(d2), "+f"(d3)
        : "r"(a0), "r"(a1), "r"(a2), "r"(a3), "r"(b0), "r"(b1));
}

#define A_BYTES 32768       // 256 rows * 128B (64 halves of k)
#define B_BYTES 16384       // 128 rows * 128B
#define STAGE_BYTES (A_BYTES + B_BYTES)
#define NSTAGE 4
#define SMEM_DYN (NSTAGE * STAGE_BYTES + 1024)
#define KITERS 36           // 2304 / 64

__global__ __launch_bounds__(256, 1)
void modconv_main(const __grid_constant__ CUtensorMap amap,
                  const __grid_constant__ CUtensorMap bmap,
                  float* __restrict__ out) {
    extern __shared__ char smem[];
    __shared__ __align__(8) unsigned long long bar_store[2 * NSTAGE];
    __shared__ float s_dmod[128];

    const uint32_t S = (smem_u32(smem) + 1023u) & ~1023u;
    const uint32_t barb = smem_u32(bar_store);

    const int tid  = threadIdx.x;
    const int wid  = tid >> 5;
    const int lane = tid & 31;

    const int n0   = blockIdx.x << 7;
    const int pos0 = blockIdx.y << 8;       // 256 rows = 4 image rows of one image
    const int b    = pos0 >> 12;
    const int h0   = (pos0 >> 6) & 63;

    if (tid == 0) {
#pragma unroll
        for (int s = 0; s < NSTAGE; ++s) {
            mbar_init(barb + 16 * s, 1);        // full[s]
            mbar_init(barb + 16 * s + 8, 8);    // empty[s]: one arrive per warp
        }
    }
    if (tid < 128) s_dmod[tid] = g_dmod[b * CO + n0 + tid];
    __syncthreads();

    auto issue = [&](int kt) {
        const int s = kt & 3;
        mbar_wait_relaxed(barb + 16 * s + 8, ((kt >> 2) & 1) ^ 1);   // empty[s]
        const uint32_t fb = barb + 16 * s;
        mbar_expect_tx(fb, STAGE_BYTES);
        const int tap = kt >> 2;                  // 4 ktiles of 64 per tap
        const int ci0 = (kt & 3) * 64;
        const int dh  = tap / 3 - 1;
        const int dw  = tap - (tap / 3) * 3 - 1;
        tma4d(S + s * STAGE_BYTES, &amap, ci0, dw, h0 + dh, b, fb);
        tma2d(S + s * STAGE_BYTES + A_BYTES, &bmap, kt * 64, n0, fb);
    };

    // fragment geometry (identical byte layout to the tf32 version)
    const int g  = lane >> 3;
    const int rr = lane & 7;
    const int warpM = (wid >> 1) << 6;      // 4 M-warps
    const int warpN = (wid & 1) << 6;       // 2 N-warps
    const uint32_t swx = (uint32_t)rr << 4;
    const uint32_t a_chi = (uint32_t)(g >> 1) << 4;
    const uint32_t b_chi = (uint32_t)(g & 1) << 4;
    const int a_rl = rr + ((g & 1) << 3);
    const int b_rl = rr + ((g >> 1) << 3);
    uint32_t a_row[4], b_row[4];
#pragma unroll
    for (int mt = 0; mt < 4; ++mt) a_row[mt] = (uint32_t)(warpM + mt * 16 + a_rl) << 7;
#pragma unroll
    for (int np = 0; np < 4; ++np) b_row[np] = (uint32_t)(warpN + np * 16 + b_rl) << 7;

    float acc[4][8][4];
#pragma unroll
    for (int mt = 0; mt < 4; ++mt)
#pragma unroll
        for (int nt = 0; nt < 8; ++nt)
#pragma unroll
            for (int i = 0; i < 4; ++i) acc[mt][nt][i] = 0.f;

    if (tid == 0) { issue(0); issue(1); issue(2); }

#pragma unroll 1
    for (int kt = 0; kt < KITERS; ++kt) {
        if (tid == 0 && kt + 3 < KITERS) issue(kt + 3);

        const int s = kt & 3;
        mbar_wait(barb + 16 * s, (kt >> 2) & 1);   // full[s]

        const uint32_t As = S + s * STAGE_BYTES;
        const uint32_t Bs = As + A_BYTES;

#pragma unroll
        for (int ks = 0; ks < 4; ++ks) {           // 4 k-steps of 16 halves (32B chunks)
            const uint32_t ca = ((uint32_t)(ks * 32) + a_chi) ^ swx;
            const uint32_t cb = ((uint32_t)(ks * 32) + b_chi) ^ swx;
            unsigned af[4][4], bf[4][4];
#pragma unroll
            for (int mt = 0; mt < 4; ++mt)
                ldsm4(af[mt][0], af[mt][1], af[mt][2], af[mt][3], As + a_row[mt] + ca);
#pragma unroll
            for (int np = 0; np < 4; ++np)
                ldsm4(bf[np][0], bf[np][1], bf[np][2], bf[np][3], Bs + b_row[np] + cb);
#pragma unroll
            for (int mt = 0; mt < 4; ++mt)
#pragma unroll
                for (int nt = 0; nt < 8; ++nt) {
                    const unsigned bb0 = bf[nt >> 1][(nt & 1) * 2];
                    const unsigned bb1 = bf[nt >> 1][(nt & 1) * 2 + 1];
                    mma_f16(acc[mt][nt][0], acc[mt][nt][1], acc[mt][nt][2], acc[mt][nt][3],
                            af[mt][0], af[mt][1], af[mt][2], af[mt][3], bb0, bb1);
                }
        }
        if (lane == 0) mbar_arrive(barb + 16 * s + 8);   // empty[s]
    }

    // epilogue: demodulate + streaming store
    const int ar = lane >> 2, ac = lane & 3;
#pragma unroll
    for (int mt = 0; mt < 4; ++mt) {
#pragma unroll
        for (int nt = 0; nt < 8; ++nt) {
            const int r = warpM + mt * 16 + ar;
            const int c = warpN + nt * 8 + ac * 2;
            const float d0 = s_dmod[c], d1 = s_dmod[c + 1];
            const size_t base = (size_t)(pos0 + r) * CO + n0 + c;
            float2 o0 = { acc[mt][nt][0] * d0, acc[mt][nt][1] * d1 };
            __stcs((float2*)&out[base], o0);
            float2 o1 = { acc[mt][nt][2] * d0, acc[mt][nt][3] * d1 };
            __stcs((float2*)&out[base + (size_t)8 * CO], o1);
        }
    }
}

// ---------------------------------------------------------------------------
typedef CUresult (*EncodeFn)(CUtensorMap*, CUtensorMapDataType, cuuint32_t, void*,
                             const cuuint64_t*, const cuuint64_t*, const cuuint32_t*,
                             const cuuint32_t*, CUtensorMapInterleave, CUtensorMapSwizzle,
                             CUtensorMapL2promotion, CUtensorMapFloatOOBfill);

extern "C" void kernel_launch(void* const* d_in, const int* in_sizes, int n_in,
                              void* d_out, int out_size) {
    const float* x     = (const float*)d_in[0];
    const float* style = (const float*)d_in[1];
    const float* kern  = (const float*)d_in[2];
    float* out = (float*)d_out;

    cudaFuncSetAttribute(modconv_main, cudaFuncAttributeMaxDynamicSharedMemorySize, SMEM_DYN);

    void* xaptr = nullptr; cudaGetSymbolAddress(&xaptr, g_xa);
    void* wtptr = nullptr; cudaGetSymbolAddress(&wtptr, g_Wt);

    EncodeFn enc = nullptr;
    cudaDriverEntryPointQueryResult qst;
    cudaGetDriverEntryPointByVersion("cuTensorMapEncodeTiled", (void**)&enc, 12000,
                                     cudaEnableDefault, &qst);
    if (!enc) {
        cudaGetDriverEntryPoint("cuTensorMapEncodeTiled", (void**)&enc,
                                cudaEnableDefault, &qst);
    }

    CUtensorMap amap, bmap;
    {   // A: g_xa (fp16) viewed as (ci=256, w=64, h=64, b=16), box (64, 64, 4, 1)
        cuuint64_t dims[4] = {256, 64, 64, 16};
        cuuint64_t strd[3] = {512, 32768, 2097152};         // bytes
        cuuint32_t box[4]  = {64, 64, 4, 1};
        cuuint32_t els[4]  = {1, 1, 1, 1};
        enc(&amap, CU_TENSOR_MAP_DATA_TYPE_UINT16, 4, xaptr, dims, strd, box, els,
            CU_TENSOR_MAP_INTERLEAVE_NONE, CU_TENSOR_MAP_SWIZZLE_128B,
            CU_TENSOR_MAP_L2_PROMOTION_L2_128B, CU_TENSOR_MAP_FLOAT_OOB_FILL_NONE);
    }
    {   // B: g_Wt (fp16) viewed as (k=2304, co=256), box (64, 128)
        cuuint64_t dims[2] = {2304, 256};
        cuuint64_t strd[1] = {4608};                        // bytes
        cuuint32_t box[2]  = {64, 128};
        cuuint32_t els[2]  = {1, 1};
        enc(&bmap, CU_TENSOR_MAP_DATA_TYPE_UINT16, 2, wtptr, dims, strd, box, els,
            CU_TENSOR_MAP_INTERLEAVE_NONE, CU_TENSOR_MAP_SWIZZLE_128B,
            CU_TENSOR_MAP_L2_PROMOTION_L2_128B, CU_TENSOR_MAP_FLOAT_OOB_FILL_NONE);
    }

    k2_kernel<<<CI, CO>>>(kern);
    dmod_kernel<<<BB, CO>>>(style);
    wt_kernel<<<dim3(KTOT / 32, CO / 32), dim3(32, 8)>>>(kern);
    xa_kernel<<<(NPOS * CI) / 2048, 256>>>(x, style);

    modconv_main<<<dim3(2, NPOS / 256), 256, SMEM_DYN>>>(amap, bmap, out);
}